// round 16
// baseline (speedup 1.0000x reference)
#include <cuda_runtime.h>
#include <cuda_fp16.h>
#include <cstdint>
#include <math.h>

// ---------------- device scratch (allocation-free) ----------------
__device__ __align__(16) __half g_ub [512 * 1024];   // fp16(expm1(u[k][n])), [k][n]
__device__ __align__(16) __half g_Ef [256 * 512];    // fp16(E)
__device__ float g_rs[16 * 256];                     // per-(ntile,row) rowsums of E
// monotonic producer counters (replay-safe via ticket targets; never reset)
__device__ unsigned g_ecnt[8];
__device__ unsigned g_ucnt;

// ---------------- helpers ----------------
__device__ __forceinline__ uint32_t smem_u32(const void* p) {
    uint32_t a;
    asm("{ .reg .u64 t; cvta.to.shared.u64 t, %1; cvt.u32.u64 %0, t; }" : "=r"(a) : "l"(p));
    return a;
}
__device__ __forceinline__ void cp16(uint32_t dst, const void* src) {
    asm volatile("cp.async.cg.shared.global [%0], [%1], 16;" :: "r"(dst), "l"(src) : "memory");
}
#define CP_COMMIT() asm volatile("cp.async.commit_group;" ::: "memory")
#define CP_WAITN(n) asm volatile("cp.async.wait_group %0;" :: "n"(n) : "memory")

__device__ __forceinline__ void ldsm4(uint32_t* r, uint32_t addr) {
    asm volatile("ldmatrix.sync.aligned.m8n8.x4.shared.b16 {%0,%1,%2,%3}, [%4];"
        : "=r"(r[0]), "=r"(r[1]), "=r"(r[2]), "=r"(r[3]) : "r"(addr));
}
__device__ __forceinline__ void ldsm4t(uint32_t* r, uint32_t addr) {
    asm volatile("ldmatrix.sync.aligned.m8n8.x4.trans.shared.b16 {%0,%1,%2,%3}, [%4];"
        : "=r"(r[0]), "=r"(r[1]), "=r"(r[2]), "=r"(r[3]) : "r"(addr));
}
__device__ __forceinline__ void mma_f16(float* c, const uint32_t* a, uint32_t b0, uint32_t b1) {
    asm volatile("mma.sync.aligned.m16n8k16.row.col.f32.f16.f16.f32 "
        "{%0,%1,%2,%3}, {%4,%5,%6,%7}, {%8,%9}, {%0,%1,%2,%3};"
        : "+f"(c[0]), "+f"(c[1]), "+f"(c[2]), "+f"(c[3])
        : "r"(a[0]), "r"(a[1]), "r"(a[2]), "r"(a[3]), "r"(b0), "r"(b1));
}

__device__ __forceinline__ uint32_t pack_h2(float a, float b) {
    __half2 h = __floats2half2_rn(a, b);
    return *(uint32_t*)&h;
}
// expm1 for u in [0,1e-3]: 3 FFMA, no MUFU
__device__ __forceinline__ float expm1_small(float u) {
    return u * fmaf(u, fmaf(u, 0.16666667f, 0.5f), 1.0f);
}
__device__ __forceinline__ uint32_t poly_pack2(float a, float b) {
    return pack_h2(expm1_small(a), expm1_small(b));
}

// release-ordered arrival; returns ticket (old value)
__device__ __forceinline__ unsigned atom_add_release(unsigned* p) {
    unsigned old;
    asm volatile("atom.add.release.gpu.u32 %0, [%1], %2;"
        : "=r"(old) : "l"(p), "r"(1u) : "memory");
    return old;
}
// spin until *cnt >= target (wrap-safe compare)
__device__ __forceinline__ void spin_until(const unsigned* cnt, unsigned target) {
    unsigned v;
    while (true) {
        asm volatile("ld.acquire.gpu.global.b32 %0, [%1];" : "=r"(v) : "l"(cnt) : "memory");
        if ((int)(v - target) >= 0) break;
        __nanosleep(32);
    }
}

// ---------------- smem layout ----------------
constexpr int P      = 136;                  // f16 row pitch (272 B)
constexpr int PF     = 136;                  // f32 row pitch (544 B)
constexpr int F32TA  = 32 * PF * 4;          // 17408 B  (one 32x128 f32 tile)
constexpr int F32STG = 2 * F32TA;            // 34816 B (A|B f32), 4-stage ring = 139264
constexpr int F16_OFF = 4 * F32STG;          // 139264
constexpr int F16TA  = 32 * P * 2;           // 8704 B
constexpr int F16STG = 2 * F16TA;            // 17408 B (A|B f16), 2-slot ring = 34816
// P2 stages (alias over P1 rings, used after E-flag)
constexpr int ET2B   = 32 * P * 2;           // 8704 B
constexpr int UT2B   = 128 * P * 2;          // 34816 B
constexpr int STG2B  = ET2B + UT2B;          // 43520 B, 4 stages = 174080
constexpr int RED_OFF = 174080;              // = F16_OFF + 2*F16STG = 4*STG2B
constexpr int DSMEM   = RED_OFF + 24576 + 256;

// ============================================================
// Fused: P1 consumes x,W f32 DIRECTLY via cp.async + in-smem convert
// (no gmem scratch, no x/W flags). u converted under P1's fill; E flagged.
// 128 CTAs x 512 thr (16 warps: 2wn x 2wm x 4wk), 1 CTA/SM.
// ============================================================
__global__ __launch_bounds__(512) void fused_kernel(
    const float* __restrict__ x, const float* __restrict__ W,
    const float* __restrict__ u, float* __restrict__ Y)
{
    extern __shared__ __align__(16) char smem[];
    const uint32_t sb = smem_u32(smem);
    float* sredf = (float*)(smem + RED_OFF);

    const int tid = threadIdx.x, lane = tid & 31, wid = tid >> 5;
    const int blk = blockIdx.x;
    const int nt = blk & 15;
    const int mt = blk >> 4;
    const int m0 = mt * 32, n0 = nt * 32;

    unsigned tu_target = 0;

    // ---- P1 loader mapping: f32 tiles, 4 cp16/thread/chunk ----
    const int rowT = tid >> 4;                 // 0..31
    const int segT = tid & 15;                 // 4-f32 segment (covers segT and segT+16)
    const float* aSf = x + (m0 + rowT) * 1024 + segT * 4;
    const float* bSf = W + (n0 + rowT) * 1024 + segT * 4;
    const uint32_t aDf = sb + (uint32_t)((rowT * PF + segT * 4) * 4);
    const uint32_t bDf = sb + (uint32_t)(F32TA + (rowT * PF + segT * 4) * 4);

    #define G1_ISSUE(c) do { \
        const uint32_t _so = ((c) & 3) * F32STG; \
        const float* _a = aSf + (c) * 128; \
        const float* _b = bSf + (c) * 128; \
        cp16(aDf + _so,       _a); \
        cp16(aDf + _so + 256, _a + 64); \
        cp16(bDf + _so,       _b); \
        cp16(bDf + _so + 256, _b + 64); \
        CP_COMMIT(); \
    } while (0)

    // prefetch first 3 f32 stages immediately (cold-DRAM latency starts now)
    G1_ISSUE(0); G1_ISSUE(1); G1_ISSUE(2);

    // ---- u rider: LDG hides under the in-flight cp.asyncs ----
    {
        const int iu = blk * 1024 + tid * 2;
        float4 uv0 = ((const float4*)u)[iu];
        float4 uv1 = ((const float4*)u)[iu + 1];
        *(uint4*)&g_ub[iu * 4] = make_uint4(poly_pack2(uv0.x, uv0.y), poly_pack2(uv0.z, uv0.w),
                                            poly_pack2(uv1.x, uv1.y), poly_pack2(uv1.z, uv1.w));
    }
    __threadfence();
    __syncthreads();
    if (tid == 0) {
        unsigned vu = atom_add_release(&g_ucnt);
        tu_target = vu - (vu & 127u) + 128u;
    }

    // ---- compute mapping: 16 warps = 2(wn) x 2(wm) x 4(wk) ----
    const int wn = wid & 1, wm = (wid >> 1) & 1, wk = wid >> 2;
    const int lrow = lane & 15;
    const int lk = (lane >> 4) << 3;
    const uint32_t aOff = (uint32_t)(((wm * 16 + lrow) * P + lk) * 2);
    const uint32_t bOff = (uint32_t)(F16TA + ((wn * 16 + lrow) * P + lk) * 2);

    // convert mapping: thread handles 8 f32 of A-row and B-row at (rowT, segT*8)
    const uint32_t cvA_src = (uint32_t)((rowT * PF + segT * 8) * 4);
    const uint32_t cvA_dst = (uint32_t)((rowT * P + segT * 8) * 2);

    float acc0[4] = {}, acc1[4] = {};

    // =================== PHASE 1 mainloop ===================
    #pragma unroll
    for (int c = 0; c < 8; c++) {
        if (c <= 5) CP_WAITN(2);
        else if (c == 6) CP_WAITN(1);
        else CP_WAITN(0);
        __syncthreads();
        // convert f32 stage (c&3) -> f16 slot (c&1)
        {
            char* f32s = smem + (c & 3) * F32STG;
            char* f16s = smem + F16_OFF + (c & 1) * F16STG;
            float4 a0 = *(const float4*)(f32s + cvA_src);
            float4 a1 = *(const float4*)(f32s + cvA_src + 16);
            float4 b0 = *(const float4*)(f32s + F32TA + cvA_src);
            float4 b1 = *(const float4*)(f32s + F32TA + cvA_src + 16);
            *(uint4*)(f16s + cvA_dst) =
                make_uint4(pack_h2(a0.x, a0.y), pack_h2(a0.z, a0.w),
                           pack_h2(a1.x, a1.y), pack_h2(a1.z, a1.w));
            *(uint4*)(f16s + F16TA + cvA_dst) =
                make_uint4(pack_h2(b0.x, b0.y), pack_h2(b0.z, b0.w),
                           pack_h2(b1.x, b1.y), pack_h2(b1.z, b1.w));
        }
        if (c + 3 < 8) G1_ISSUE(c + 3);
        __syncthreads();
        const uint32_t st = sb + F16_OFF + (c & 1) * F16STG;
        #pragma unroll
        for (int j = 0; j < 2; j++) {
            const int ks = wk * 2 + j;         // 0..7 ksteps of 16
            uint32_t a[4], b[4];
            ldsm4(a, st + aOff + ks * 32);
            ldsm4(b, st + bOff + ks * 32);
            mma_f16(acc0, a, b[0], b[2]);
            mma_f16(acc1, a, b[1], b[3]);
        }
    }
    #undef G1_ISSUE

    // 4-way k-split reduction: sred1[12][32][8]
    float (*sred1)[32][8] = (float(*)[32][8])sredf;
    float (*srs)[32] = (float(*)[32])(smem + RED_OFF + 12288);
    __syncthreads();
    if (wk != 0) {
        #pragma unroll
        for (int i = 0; i < 4; i++) {
            sred1[(wk - 1) * 4 + (wid & 3)][lane][i]     = acc0[i];
            sred1[(wk - 1) * 4 + (wid & 3)][lane][4 + i] = acc1[i];
        }
    }
    __syncthreads();

    if (wk == 0) {
        #pragma unroll
        for (int q = 0; q < 3; q++)
            #pragma unroll
            for (int i = 0; i < 4; i++) {
                acc0[i] += sred1[q * 4 + wid][lane][i];
                acc1[i] += sred1[q * 4 + wid][lane][4 + i];
            }
        // epilogue: __expf, fp16 E, fp32 rowsum
        const int qr = lane >> 2;
        const int qc = (lane & 3) * 2;
        const int mrow0 = m0 + wm * 16 + qr;
        const int mrow1 = mrow0 + 8;
        float p0 = 0.f, p1 = 0.f;
        #pragma unroll
        for (int g = 0; g < 2; g++) {
            float* acc = g ? acc1 : acc0;
            float e0 = __expf(acc[0]), e1 = __expf(acc[1]);
            float e2 = __expf(acc[2]), e3 = __expf(acc[3]);
            p0 += e0 + e1; p1 += e2 + e3;
            const int n = n0 + wn * 16 + g * 8 + qc;
            *(uint32_t*)&g_Ef[mrow0 * 512 + n] = pack_h2(e0, e1);
            *(uint32_t*)&g_Ef[mrow1 * 512 + n] = pack_h2(e2, e3);
        }
        p0 += __shfl_xor_sync(0xFFFFFFFFu, p0, 1);
        p0 += __shfl_xor_sync(0xFFFFFFFFu, p0, 2);
        p1 += __shfl_xor_sync(0xFFFFFFFFu, p1, 1);
        p1 += __shfl_xor_sync(0xFFFFFFFFu, p1, 2);
        if ((lane & 3) == 0) {
            srs[wn][wm * 16 + qr]     = p0;
            srs[wn][wm * 16 + qr + 8] = p1;
        }
    }
    __syncthreads();
    if (tid < 32) g_rs[nt * 256 + m0 + tid] = srs[0][tid] + srs[1][tid];

    // =================== E ready: arrive + wait for same-mt peers ===================
    __threadfence();
    __syncthreads();
    if (tid == 0) {
        unsigned ve = atom_add_release(&g_ecnt[mt]);
        spin_until(&g_ecnt[mt], ve - (ve & 15u) + 16u);
        spin_until(&g_ucnt, tu_target);       // long satisfied by now
    }
    __syncthreads();

    // =================== PHASE 2: y = E @ ub + rowsum + 512 ===================
    const int n0b = nt * 64;

    float* rst = (float*)(smem + RED_OFF + 24576);
    if (tid < 32) {
        float s = 512.0f;
        #pragma unroll
        for (int j = 0; j < 16; j++) s += g_rs[j * 256 + m0 + tid];
        rst[tid] = s;
    }

    // loaders: E 1 cp16/thread, u 2 cp16/thread per chunk (K=128 chunks)
    const int rowE = tid >> 4, segE = tid & 15;
    const __half* aSrc = g_Ef + (m0 + rowE) * 512 + segE * 8;
    const uint32_t aDst = sb + (uint32_t)((rowE * P + segE * 8) * 2);
    const int uIdx0 = tid * 2, uIdx1 = tid * 2 + 1;
    const int kr0 = uIdx0 >> 3, sg0 = uIdx0 & 7;
    const int kr1 = uIdx1 >> 3, sg1 = uIdx1 & 7;
    const __half* bSrc0 = g_ub + kr0 * 1024 + n0b + sg0 * 8;
    const __half* bSrc1 = g_ub + kr1 * 1024 + n0b + sg1 * 8;
    const uint32_t bDst0 = sb + (uint32_t)(ET2B + (kr0 * P + sg0 * 8) * 2);
    const uint32_t bDst1 = sb + (uint32_t)(ET2B + (kr1 * P + sg1 * 8) * 2);

    #define G2_ISSUE(c) do { \
        const uint32_t _so = (c) * STG2B; \
        cp16(aDst + _so, aSrc + (c) * 128); \
        cp16(bDst0 + _so, bSrc0 + (c) * 128 * 1024); \
        cp16(bDst1 + _so, bSrc1 + (c) * 128 * 1024); \
        CP_COMMIT(); \
    } while (0)

    const uint32_t a2Off = (uint32_t)(((wm * 16 + lrow) * P + lk) * 2);
    const int li = lane & 7, kbit = (lane >> 3) & 1, nq = lane >> 4;
    const uint32_t tOff = (uint32_t)((((kbit * 8 + li) * P) + nq * 8) * 2);

    float acc[4][4] = {};

    G2_ISSUE(0); G2_ISSUE(1); G2_ISSUE(2); G2_ISSUE(3);
    #undef G2_ISSUE

    #pragma unroll
    for (int c = 0; c < 4; c++) {
        if (c == 0) CP_WAITN(3);
        else if (c == 1) CP_WAITN(2);
        else if (c == 2) CP_WAITN(1);
        else CP_WAITN(0);
        __syncthreads();
        const uint32_t st = sb + c * STG2B;
        const uint32_t stU = st + ET2B;
        #pragma unroll
        for (int j = 0; j < 2; j++) {
            const int ks = wk * 2 + j;
            uint32_t a[4], bq0[4], bq1[4];
            ldsm4(a, st + a2Off + ks * 32);
            ldsm4t(bq0, stU + tOff + ks * 16 * P * 2 + (wn * 32 + 0) * 2);
            ldsm4t(bq1, stU + tOff + ks * 16 * P * 2 + (wn * 32 + 16) * 2);
            mma_f16(acc[0], a, bq0[0], bq0[1]);
            mma_f16(acc[1], a, bq0[2], bq0[3]);
            mma_f16(acc[2], a, bq1[0], bq1[1]);
            mma_f16(acc[3], a, bq1[2], bq1[3]);
        }
    }

    // k-split reduction: sred2[12][32][16]
    float (*sred2)[32][16] = (float(*)[32][16])sredf;
    __syncthreads();
    if (wk != 0) {
        #pragma unroll
        for (int g = 0; g < 4; g++)
            #pragma unroll
            for (int i = 0; i < 4; i++)
                sred2[(wk - 1) * 4 + (wid & 3)][lane][g * 4 + i] = acc[g][i];
    }
    __syncthreads();

    if (wk == 0) {
        #pragma unroll
        for (int q = 0; q < 3; q++)
            #pragma unroll
            for (int g = 0; g < 4; g++)
                #pragma unroll
                for (int i = 0; i < 4; i++)
                    acc[g][i] += sred2[q * 4 + wid][lane][g * 4 + i];

        const int qr = lane >> 2;
        const int qc = (lane & 3) * 2;
        const int mrow0 = m0 + wm * 16 + qr;
        const int mrow1 = mrow0 + 8;
        const float r0v = rst[wm * 16 + qr];
        const float r1v = rst[wm * 16 + qr + 8];
        #pragma unroll
        for (int g = 0; g < 4; g++) {
            const int n = n0b + wn * 32 + g * 8 + qc;
            *(float2*)(Y + mrow0 * 1024 + n) = make_float2(acc[g][0] + r0v, acc[g][1] + r0v);
            *(float2*)(Y + mrow1 * 1024 + n) = make_float2(acc[g][2] + r1v, acc[g][3] + r1v);
        }
    }
}

// ============================================================
extern "C" void kernel_launch(void* const* d_in, const int* in_sizes, int n_in,
                              void* d_out, int out_size)
{
    const float* x = (const float*)d_in[0];   // 256 x 1024
    const float* W = (const float*)d_in[1];   // 512 x 1024
    const float* u = (const float*)d_in[2];   // 512 x 1024
    float* y = (float*)d_out;                 // 256 x 1024

    cudaFuncSetAttribute(fused_kernel, cudaFuncAttributeMaxDynamicSharedMemorySize, DSMEM);
    fused_kernel<<<128, 512, DSMEM>>>(x, W, u, y);
}

// round 17
// speedup vs baseline: 1.0928x; 1.0928x over previous
#include <cuda_runtime.h>
#include <cuda_fp16.h>
#include <cstdint>
#include <math.h>

// ---------------- device scratch (allocation-free) ----------------
__device__ __align__(16) __half g_xh [256 * 1024];   // fp16(x)
__device__ __align__(16) __half g_Wh [512 * 1024];   // fp16(W)
__device__ __align__(16) __half g_ub [512 * 1024];   // fp16(expm1(u[k][n])), [k][n]
__device__ __align__(16) __half g_Ef [256 * 512];    // fp16(E)
__device__ float g_rs[16 * 256];                     // per-(ntile,row) rowsums of E
// monotonic producer counters (replay-safe via ticket targets; never reset)
__device__ unsigned g_xcnt[8];
__device__ unsigned g_wcnt[16];
__device__ unsigned g_ecnt[8];
__device__ unsigned g_ucnt;

// ---------------- helpers ----------------
__device__ __forceinline__ uint32_t smem_u32(const void* p) {
    uint32_t a;
    asm("{ .reg .u64 t; cvta.to.shared.u64 t, %1; cvt.u32.u64 %0, t; }" : "=r"(a) : "l"(p));
    return a;
}
__device__ __forceinline__ void cp16(uint32_t dst, const void* src) {
    asm volatile("cp.async.cg.shared.global [%0], [%1], 16;" :: "r"(dst), "l"(src) : "memory");
}
#define CP_COMMIT() asm volatile("cp.async.commit_group;" ::: "memory")
#define CP_WAITN(n) asm volatile("cp.async.wait_group %0;" :: "n"(n) : "memory")

__device__ __forceinline__ void ldsm4(uint32_t* r, uint32_t addr) {
    asm volatile("ldmatrix.sync.aligned.m8n8.x4.shared.b16 {%0,%1,%2,%3}, [%4];"
        : "=r"(r[0]), "=r"(r[1]), "=r"(r[2]), "=r"(r[3]) : "r"(addr));
}
__device__ __forceinline__ void ldsm4t(uint32_t* r, uint32_t addr) {
    asm volatile("ldmatrix.sync.aligned.m8n8.x4.trans.shared.b16 {%0,%1,%2,%3}, [%4];"
        : "=r"(r[0]), "=r"(r[1]), "=r"(r[2]), "=r"(r[3]) : "r"(addr));
}
__device__ __forceinline__ void mma_f16(float* c, const uint32_t* a, uint32_t b0, uint32_t b1) {
    asm volatile("mma.sync.aligned.m16n8k16.row.col.f32.f16.f16.f32 "
        "{%0,%1,%2,%3}, {%4,%5,%6,%7}, {%8,%9}, {%0,%1,%2,%3};"
        : "+f"(c[0]), "+f"(c[1]), "+f"(c[2]), "+f"(c[3])
        : "r"(a[0]), "r"(a[1]), "r"(a[2]), "r"(a[3]), "r"(b0), "r"(b1));
}

__device__ __forceinline__ uint32_t pack_h2(float a, float b) {
    __half2 h = __floats2half2_rn(a, b);
    return *(uint32_t*)&h;
}
// expm1 for u in [0,1e-3]: 3 FFMA, no MUFU
__device__ __forceinline__ float expm1_small(float u) {
    return u * fmaf(u, fmaf(u, 0.16666667f, 0.5f), 1.0f);
}
__device__ __forceinline__ uint32_t poly_pack2(float a, float b) {
    return pack_h2(expm1_small(a), expm1_small(b));
}

// release-ordered arrival; returns ticket (old value)
__device__ __forceinline__ unsigned atom_add_release(unsigned* p) {
    unsigned old;
    asm volatile("atom.add.release.gpu.u32 %0, [%1], %2;"
        : "=r"(old) : "l"(p), "r"(1u) : "memory");
    return old;
}
// spin until *cnt >= target (wrap-safe compare)
__device__ __forceinline__ void spin_until(const unsigned* cnt, unsigned target) {
    unsigned v;
    while (true) {
        asm volatile("ld.acquire.gpu.global.b32 %0, [%1];" : "=r"(v) : "l"(cnt) : "memory");
        if ((int)(v - target) >= 0) break;
        __nanosleep(32);
    }
}

// ---------------- smem layout ----------------
constexpr int P      = 136;                  // 16-bit elem row pitch (272 B)
constexpr int T1B    = 32 * P * 2;           // 8704 B  (one 32x128 f16 tile)
constexpr int STG1B  = 2 * T1B;              // 17408 B (A|B), 8 stages = 139264
constexpr int ET2B   = 32 * P * 2;           // 8704 B
constexpr int UT2B   = 128 * P * 2;          // 34816 B
constexpr int STG2B  = ET2B + UT2B;          // 43520 B, 4 stages = 174080
constexpr int RED_OFF = 4 * STG2B;           // 174080 (P1's 8 stages fit inside)
constexpr int DSMEM   = RED_OFF + 24576 + 256;

// ============================================================
// Fused, flag-synchronized, barrier-free mainloops:
//  P0: tile-owned conversion  x,W -> f16; u -> f16(expm1)
//  P1: E = exp(x@W^T), 8 distinct stages, ONE wait+barrier, no intra-loop syncs
//  P2: y = E @ ub + rowsum(E) + 512, 4 distinct stages, ONE wait+barrier
// 128 CTAs x 512 thr (16 warps: 2wn x 2wm x 4wk), 1 CTA/SM.
// ============================================================
__global__ __launch_bounds__(512) void fused_kernel(
    const float* __restrict__ x, const float* __restrict__ W,
    const float* __restrict__ u, float* __restrict__ Y)
{
    extern __shared__ __align__(16) char smem[];
    const uint32_t sb = smem_u32(smem);
    float* sredf = (float*)(smem + RED_OFF);

    const int tid = threadIdx.x, lane = tid & 31, wid = tid >> 5;
    const int blk = blockIdx.x;
    const int nt = blk & 15;
    const int mt = blk >> 4;
    const int m0 = mt * 32, n0 = nt * 32;

    unsigned tu_target = 0;

    // =================== PHASE 0: tile-owned conversion ===================
    {
        // x: this CTA converts segment nt of x-tile mt (1 f4/thread)
        const int ix = mt * 8192 + nt * 512 + tid;
        float4 xv = ((const float4*)x)[ix];
        // W: segment mt of W-tile nt (2 consecutive f4/thread)
        const int iw = nt * 8192 + mt * 1024 + tid * 2;
        float4 wv0 = ((const float4*)W)[iw];
        float4 wv1 = ((const float4*)W)[iw + 1];
        // u: linear 1/128 (2 consecutive f4/thread)
        const int iu = blk * 1024 + tid * 2;
        float4 uv0 = ((const float4*)u)[iu];
        float4 uv1 = ((const float4*)u)[iu + 1];

        *(uint2*)&g_xh[ix * 4] = make_uint2(pack_h2(xv.x, xv.y), pack_h2(xv.z, xv.w));
        *(uint4*)&g_Wh[iw * 4] = make_uint4(pack_h2(wv0.x, wv0.y), pack_h2(wv0.z, wv0.w),
                                            pack_h2(wv1.x, wv1.y), pack_h2(wv1.z, wv1.w));
        *(uint4*)&g_ub[iu * 4] = make_uint4(poly_pack2(uv0.x, uv0.y), poly_pack2(uv0.z, uv0.w),
                                            poly_pack2(uv1.x, uv1.y), poly_pack2(uv1.z, uv1.w));
    }
    __threadfence();
    __syncthreads();
    if (tid == 0) {
        unsigned vx = atom_add_release(&g_xcnt[mt]);
        unsigned vw = atom_add_release(&g_wcnt[nt]);
        unsigned vu = atom_add_release(&g_ucnt);
        tu_target = vu - (vu & 127u) + 128u;
        spin_until(&g_xcnt[mt], vx - (vx & 15u) + 16u);
        spin_until(&g_wcnt[nt], vw - (vw & 7u) + 8u);
    }
    __syncthreads();

    // =================== PHASE 1: E = exp(x @ W^T) ===================
    const int rowT = tid >> 4;                 // 0..31
    const int segT = tid & 15;                 // 16B segment
    const __half* aS = g_xh + (m0 + rowT) * 1024 + segT * 8;
    const __half* bS = g_Wh + (n0 + rowT) * 1024 + segT * 8;
    const uint32_t aD = sb + (uint32_t)((rowT * P + segT * 8) * 2);
    const uint32_t bD = sb + (uint32_t)(T1B + (rowT * P + segT * 8) * 2);

    #define G1_ISSUE(c) do { \
        const uint32_t _so = (c) * STG1B; \
        cp16(aD + _so, aS + (c) * 128); \
        cp16(bD + _so, bS + (c) * 128); \
    } while (0)

    // compute mapping: 16 warps = 2(wn) x 2(wm) x 4(wk)
    const int wn = wid & 1, wm = (wid >> 1) & 1, wk = wid >> 2;
    const int lrow = lane & 15;
    const int lk = (lane >> 4) << 3;
    const uint32_t aOff = (uint32_t)(((wm * 16 + lrow) * P + lk) * 2);
    const uint32_t bOff = (uint32_t)(T1B + ((wn * 16 + lrow) * P + lk) * 2);

    float acc0[4] = {}, acc1[4] = {};

    // prefetch ALL 8 stages (full K=1024), single commit group
    G1_ISSUE(0); G1_ISSUE(1); G1_ISSUE(2); G1_ISSUE(3);
    G1_ISSUE(4); G1_ISSUE(5); G1_ISSUE(6); G1_ISSUE(7);
    CP_COMMIT();
    #undef G1_ISSUE

    // ONE wait + ONE barrier; 8 distinct buffers -> no intra-loop syncs
    CP_WAITN(0);
    __syncthreads();

    #pragma unroll
    for (int c = 0; c < 8; c++) {
        const uint32_t st = sb + c * STG1B;
        #pragma unroll
        for (int j = 0; j < 2; j++) {
            const int ks = wk * 2 + j;         // 0..7 ksteps of 16
            uint32_t a[4], b[4];
            ldsm4(a, st + aOff + ks * 32);
            ldsm4(b, st + bOff + ks * 32);
            mma_f16(acc0, a, b[0], b[2]);
            mma_f16(acc1, a, b[1], b[3]);
        }
    }

    // 4-way k-split reduction: sred1[12][32][8]
    float (*sred1)[32][8] = (float(*)[32][8])sredf;
    float (*srs)[32] = (float(*)[32])(smem + RED_OFF + 12288);
    __syncthreads();
    if (wk != 0) {
        #pragma unroll
        for (int i = 0; i < 4; i++) {
            sred1[(wk - 1) * 4 + (wid & 3)][lane][i]     = acc0[i];
            sred1[(wk - 1) * 4 + (wid & 3)][lane][4 + i] = acc1[i];
        }
    }
    __syncthreads();

    if (wk == 0) {
        #pragma unroll
        for (int q = 0; q < 3; q++)
            #pragma unroll
            for (int i = 0; i < 4; i++) {
                acc0[i] += sred1[q * 4 + wid][lane][i];
                acc1[i] += sred1[q * 4 + wid][lane][4 + i];
            }
        // epilogue: __expf, fp16 E, fp32 rowsum
        const int qr = lane >> 2;
        const int qc = (lane & 3) * 2;
        const int mrow0 = m0 + wm * 16 + qr;
        const int mrow1 = mrow0 + 8;
        float p0 = 0.f, p1 = 0.f;
        #pragma unroll
        for (int g = 0; g < 2; g++) {
            float* acc = g ? acc1 : acc0;
            float e0 = __expf(acc[0]), e1 = __expf(acc[1]);
            float e2 = __expf(acc[2]), e3 = __expf(acc[3]);
            p0 += e0 + e1; p1 += e2 + e3;
            const int n = n0 + wn * 16 + g * 8 + qc;
            *(uint32_t*)&g_Ef[mrow0 * 512 + n] = pack_h2(e0, e1);
            *(uint32_t*)&g_Ef[mrow1 * 512 + n] = pack_h2(e2, e3);
        }
        p0 += __shfl_xor_sync(0xFFFFFFFFu, p0, 1);
        p0 += __shfl_xor_sync(0xFFFFFFFFu, p0, 2);
        p1 += __shfl_xor_sync(0xFFFFFFFFu, p1, 1);
        p1 += __shfl_xor_sync(0xFFFFFFFFu, p1, 2);
        if ((lane & 3) == 0) {
            srs[wn][wm * 16 + qr]     = p0;
            srs[wn][wm * 16 + qr + 8] = p1;
        }
    }
    __syncthreads();
    if (tid < 32) g_rs[nt * 256 + m0 + tid] = srs[0][tid] + srs[1][tid];

    // =================== E ready: arrive + wait for same-mt peers ===================
    __threadfence();
    __syncthreads();
    if (tid == 0) {
        unsigned ve = atom_add_release(&g_ecnt[mt]);
        spin_until(&g_ecnt[mt], ve - (ve & 15u) + 16u);
        spin_until(&g_ucnt, tu_target);       // long satisfied by now
    }
    __syncthreads();

    // =================== PHASE 2: y = E @ ub + rowsum + 512 ===================
    const int n0b = nt * 64;

    float* rst = (float*)(smem + RED_OFF + 24576);
    if (tid < 32) {
        float s = 512.0f;
        #pragma unroll
        for (int j = 0; j < 16; j++) s += g_rs[j * 256 + m0 + tid];
        rst[tid] = s;
    }

    // loaders: E 1 cp16/thread, u 2 cp16/thread per chunk (K=128 chunks)
    const int rowE = tid >> 4, segE = tid & 15;
    const __half* aSrc = g_Ef + (m0 + rowE) * 512 + segE * 8;
    const uint32_t aDst = sb + (uint32_t)((rowE * P + segE * 8) * 2);
    const int uIdx0 = tid * 2, uIdx1 = tid * 2 + 1;
    const int kr0 = uIdx0 >> 3, sg0 = uIdx0 & 7;
    const int kr1 = uIdx1 >> 3, sg1 = uIdx1 & 7;
    const __half* bSrc0 = g_ub + kr0 * 1024 + n0b + sg0 * 8;
    const __half* bSrc1 = g_ub + kr1 * 1024 + n0b + sg1 * 8;
    const uint32_t bDst0 = sb + (uint32_t)(ET2B + (kr0 * P + sg0 * 8) * 2);
    const uint32_t bDst1 = sb + (uint32_t)(ET2B + (kr1 * P + sg1 * 8) * 2);

    #define G2_ISSUE(c) do { \
        const uint32_t _so = (c) * STG2B; \
        cp16(aDst + _so, aSrc + (c) * 128); \
        cp16(bDst0 + _so, bSrc0 + (c) * 128 * 1024); \
        cp16(bDst1 + _so, bSrc1 + (c) * 128 * 1024); \
    } while (0)

    const uint32_t a2Off = (uint32_t)(((wm * 16 + lrow) * P + lk) * 2);
    const int li = lane & 7, kbit = (lane >> 3) & 1, nq = lane >> 4;
    const uint32_t tOff = (uint32_t)((((kbit * 8 + li) * P) + nq * 8) * 2);

    float acc[4][4] = {};

    G2_ISSUE(0); G2_ISSUE(1); G2_ISSUE(2); G2_ISSUE(3);
    CP_COMMIT();
    #undef G2_ISSUE

    // ONE wait + ONE barrier; 4 distinct buffers -> no intra-loop syncs
    CP_WAITN(0);
    __syncthreads();

    #pragma unroll
    for (int c = 0; c < 4; c++) {
        const uint32_t st = sb + c * STG2B;
        const uint32_t stU = st + ET2B;
        #pragma unroll
        for (int j = 0; j < 2; j++) {
            const int ks = wk * 2 + j;
            uint32_t a[4], bq0[4], bq1[4];
            ldsm4(a, st + a2Off + ks * 32);
            ldsm4t(bq0, stU + tOff + ks * 16 * P * 2 + (wn * 32 + 0) * 2);
            ldsm4t(bq1, stU + tOff + ks * 16 * P * 2 + (wn * 32 + 16) * 2);
            mma_f16(acc[0], a, bq0[0], bq0[1]);
            mma_f16(acc[1], a, bq0[2], bq0[3]);
            mma_f16(acc[2], a, bq1[0], bq1[1]);
            mma_f16(acc[3], a, bq1[2], bq1[3]);
        }
    }

    // k-split reduction: sred2[12][32][16]
    float (*sred2)[32][16] = (float(*)[32][16])sredf;
    __syncthreads();
    if (wk != 0) {
        #pragma unroll
        for (int g = 0; g < 4; g++)
            #pragma unroll
            for (int i = 0; i < 4; i++)
                sred2[(wk - 1) * 4 + (wid & 3)][lane][g * 4 + i] = acc[g][i];
    }
    __syncthreads();

    if (wk == 0) {
        #pragma unroll
        for (int q = 0; q < 3; q++)
            #pragma unroll
            for (int g = 0; g < 4; g++)
                #pragma unroll
                for (int i = 0; i < 4; i++)
                    acc[g][i] += sred2[q * 4 + wid][lane][g * 4 + i];

        const int qr = lane >> 2;
        const int qc = (lane & 3) * 2;
        const int mrow0 = m0 + wm * 16 + qr;
        const int mrow1 = mrow0 + 8;
        const float r0v = rst[wm * 16 + qr];
        const float r1v = rst[wm * 16 + qr + 8];
        #pragma unroll
        for (int g = 0; g < 4; g++) {
            const int n = n0b + wn * 32 + g * 8 + qc;
            *(float2*)(Y + mrow0 * 1024 + n) = make_float2(acc[g][0] + r0v, acc[g][1] + r0v);
            *(float2*)(Y + mrow1 * 1024 + n) = make_float2(acc[g][2] + r1v, acc[g][3] + r1v);
        }
    }
}

// ============================================================
extern "C" void kernel_launch(void* const* d_in, const int* in_sizes, int n_in,
                              void* d_out, int out_size)
{
    const float* x = (const float*)d_in[0];   // 256 x 1024
    const float* W = (const float*)d_in[1];   // 512 x 1024
    const float* u = (const float*)d_in[2];   // 512 x 1024
    float* y = (float*)d_out;                 // 256 x 1024

    cudaFuncSetAttribute(fused_kernel, cudaFuncAttributeMaxDynamicSharedMemorySize, DSMEM);
    fused_kernel<<<128, 512, DSMEM>>>(x, W, u, y);
}